// round 7
// baseline (speedup 1.0000x reference)
#include <cuda_runtime.h>
#include <math.h>

#define L 2048
#define H 512
#define NSTATE 32
#define NL 4
#define INDIM 4
#define OUTDIM 3

#define NCHUNK 16
#define CLEN 128   // L / NCHUNK

// Scratch (allocation-free rule: device globals)
__device__ float g_h[L * H];   // residual stream
__device__ float g_u[L * H];   // layernorm output
__device__ float g_y[L * H];   // gelu(scan output)

// ---------------------------------------------------------------------------
// Encoder
// ---------------------------------------------------------------------------
__global__ void enc_kernel(const float* __restrict__ x,
                           const float* __restrict__ w,
                           const float* __restrict__ b) {
    int t = blockIdx.x;
    int j = threadIdx.x;
    float4 xr = *(const float4*)(x + t * INDIM);
    float4 wr = *(const float4*)(w + j * INDIM);
    g_h[t * H + j] = b[j] + xr.x * wr.x + xr.y * wr.y + xr.z * wr.z + xr.w * wr.w;
}

// ---------------------------------------------------------------------------
// LayerNorm over H=512 per row
// ---------------------------------------------------------------------------
__global__ void ln_kernel(const float* __restrict__ nw,
                          const float* __restrict__ nb) {
    int t = blockIdx.x;
    int tid = threadIdx.x;
    float v0 = g_h[t * H + tid];
    float v1 = g_h[t * H + tid + 256];
    float s = v0 + v1;
    float sq = v0 * v0 + v1 * v1;
#pragma unroll
    for (int off = 16; off; off >>= 1) {
        s  += __shfl_xor_sync(0xffffffffu, s, off);
        sq += __shfl_xor_sync(0xffffffffu, sq, off);
    }
    __shared__ float ss[8], ssq[8];
    int w = tid >> 5;
    if ((tid & 31) == 0) { ss[w] = s; ssq[w] = sq; }
    __syncthreads();
    __shared__ float m_sh, r_sh;
    if (tid == 0) {
        float S = 0.f, Q = 0.f;
#pragma unroll
        for (int i = 0; i < 8; i++) { S += ss[i]; Q += ssq[i]; }
        float m = S * (1.0f / H);
        float var = Q * (1.0f / H) - m * m;
        m_sh = m;
        r_sh = rsqrtf(var + 1e-5f);
    }
    __syncthreads();
    float m = m_sh, r = r_sh;
    g_u[t * H + tid]       = (v0 - m) * r * nw[tid]       + nb[tid];
    g_u[t * H + tid + 256] = (v1 - m) * r * nw[tid + 256] + nb[tid + 256];
}

// ---------------------------------------------------------------------------
// Discretization coefficients per (channel, lane=state)
// ---------------------------------------------------------------------------
struct SSMCoef { float are, aim, bbr, bbi, cre, cim, dv; };

__device__ __forceinline__ SSMCoef load_coef(
    const float* lre_, const float* lim_, const float* bre_, const float* bim_,
    const float* cre_, const float* cim_, const float* dvec, const float* lstep_,
    int ch, int lane)
{
    int idx = ch * NSTATE + lane;
    float lre = lre_[idx], lim = lim_[idx];
    float step = __expf(lstep_[ch]);
    float s2 = 0.5f * step;
    float dr = 1.f - s2 * lre, di = -s2 * lim;
    float inv = 1.f / (dr * dr + di * di);
    float blr = dr * inv, bli = -di * inv;
    float nr = 1.f + s2 * lre, ni = s2 * lim;
    SSMCoef c;
    c.are = blr * nr - bli * ni;
    c.aim = blr * ni + bli * nr;
    float br = bre_[idx], bi = bim_[idx];
    c.bbr = step * (blr * br - bli * bi);
    c.bbi = step * (blr * bi + bli * br);
    c.cre = cre_[idx];
    c.cim = cim_[idx];
    c.dv = dvec[ch];
    return c;
}

__device__ __forceinline__ float gelu_tanh(float yv) {
    float z = 0.7978845608028654f * fmaf(0.044715f * yv, yv * yv, yv);
    z = fminf(fmaxf(z, -15.f), 15.f);
    float e = __expf(2.f * z);
    float th = (e - 1.f) / (e + 1.f);
    return 0.5f * yv * (1.f + th);
}

// Merge-reduce helpers
__device__ __forceinline__ float merge2(float a, float b, int off, int lane) {
    float t = (lane & off) ? a : b;
    t = __shfl_xor_sync(0xffffffffu, t, off);
    return ((lane & off) ? b : a) + t;
}

__device__ __forceinline__ float reduce8(const float* acc, int lane) {
    float m01 = merge2(acc[0], acc[1], 16, lane);
    float m23 = merge2(acc[2], acc[3], 16, lane);
    float m45 = merge2(acc[4], acc[5], 16, lane);
    float m67 = merge2(acc[6], acc[7], 16, lane);
    float n0  = merge2(m01, m23, 8, lane);
    float n1  = merge2(m45, m67, 8, lane);
    float p   = merge2(n0, n1, 4, lane);
    p += __shfl_xor_sync(0xffffffffu, p, 2);
    p += __shfl_xor_sync(0xffffffffu, p, 1);
    return p;
}

// ---------------------------------------------------------------------------
// Fused scan: one block per channel (512 threads = 16 warps, warp = chunk).
// ---------------------------------------------------------------------------
__global__ __launch_bounds__(512) void scan_fused_kernel(
        const float* __restrict__ lre_, const float* __restrict__ lim_,
        const float* __restrict__ bre_, const float* __restrict__ bim_,
        const float* __restrict__ cre_, const float* __restrict__ cim_,
        const float* __restrict__ dvec, const float* __restrict__ lstep_) {
    __shared__ float2 st[NCHUNK][NSTATE];

    int ch = blockIdx.x;
    int wid = threadIdx.x >> 5;      // chunk
    int lane = threadIdx.x & 31;     // state

    SSMCoef cf = load_coef(lre_, lim_, bre_, bim_, cre_, cim_, dvec, lstep_, ch, lane);
    int myk = ((lane >> 4) & 1) | (((lane >> 3) & 1) << 1) | (((lane >> 2) & 1) << 2);

    int tbase = wid * CLEN;
    const float* up = g_u + ch;
    float* yp = g_y + ch;

    float yreg[16];
    float sre = 0.f, sim = 0.f;

    // ---- Phase A: local scan ----
#pragma unroll
    for (int b = 0; b < 16; b++) {
        int t0 = tbase + b * 8;
        float acc[8], uk[8];
#pragma unroll
        for (int k = 0; k < 8; k++) {
            float u = __ldg(up + (t0 + k) * H);
            float t1 = fmaf(cf.bbr, u, fmaf(-cf.aim, sim, cf.are * sre));
            float t2 = fmaf(cf.bbi, u, fmaf(cf.aim, sre, cf.are * sim));
            sre = t1; sim = t2;
            acc[k] = fmaf(-cf.cim, sim, cf.cre * sre);
            uk[k] = u;
        }
        float red = reduce8(acc, lane);
        float s01 = (lane & 16) ? uk[1] : uk[0];
        float s23 = (lane & 16) ? uk[3] : uk[2];
        float s45 = (lane & 16) ? uk[5] : uk[4];
        float s67 = (lane & 16) ? uk[7] : uk[6];
        float t0s = (lane & 8) ? s23 : s01;
        float t1s = (lane & 8) ? s67 : s45;
        float usel = (lane & 4) ? t1s : t0s;
        yreg[b] = fmaf(cf.dv, usel, 2.f * red);
    }
    st[wid][lane] = make_float2(sre, sim);
    __syncthreads();

    // ---- Phase B: sequential chunk combine (warp 0) ----
    if (wid == 0) {
        float pr = cf.are, pi = cf.aim;
#pragma unroll
        for (int i = 0; i < 7; i++) {   // A^128
            float nr = pr * pr - pi * pi;
            float ni = 2.f * pr * pi;
            pr = nr; pi = ni;
        }
        float cr = 0.f, ci = 0.f;
#pragma unroll
        for (int c = 0; c < NCHUNK; c++) {
            float2 f = st[c][lane];
            st[c][lane] = make_float2(cr, ci);
            float nr = fmaf(pr, cr, fmaf(-pi, ci, f.x));
            float ni = fmaf(pr, ci, fmaf(pi, cr, f.y));
            cr = nr; ci = ni;
        }
    }
    __syncthreads();

    // ---- Phase C: correction + gelu + store ----
    float2 si = st[wid][lane];
    float er = cf.cre * si.x - cf.cim * si.y;
    float ei = cf.cre * si.y + cf.cim * si.x;
    float wr = 1.f, wi = 0.f;

#pragma unroll
    for (int b = 0; b < 16; b++) {
        float acc[8];
#pragma unroll
        for (int k = 0; k < 8; k++) {
            float nr = cf.are * wr - cf.aim * wi;
            float ni = cf.are * wi + cf.aim * wr;
            wr = nr; wi = ni;
            acc[k] = er * wr - ei * wi;
        }
        float corr = reduce8(acc, lane);
        float yv = yreg[b] + 2.f * corr;
        if ((lane & 3) == 0)
            yp[(tbase + b * 8 + myk) * H] = gelu_tanh(yv);
    }
}

// ---------------------------------------------------------------------------
// Fused dual GEMM + gate + residual, using packed fp32 FFMA2 (fma.rn.f32x2).
// BM=64, BN=32, BK=32, 128 threads, 512 blocks, double-buffered smem.
// Accumulators hold m-pairs in 64-bit regs; B smem is value-duplicated so a
// single LDS.128 yields broadcast pairs (no pack instructions in the loop).
// ---------------------------------------------------------------------------
#define BM 64
#define BN 32
#define BK 32
#define APAD 68          // 64 + 4 floats; row = 272B (16B-aligned)
#define BDUP 68          // 64 dup floats + 4 pad
#define NKIT (H / BK)

typedef unsigned long long u64t;

__device__ __forceinline__ u64t ffma2(u64t a, u64t b, u64t c) {
    u64t d;
    asm("fma.rn.f32x2 %0, %1, %2, %3;" : "=l"(d) : "l"(a), "l"(b), "l"(c));
    return d;
}

__device__ __forceinline__ float lo32(u64t v) {
    return __uint_as_float((unsigned)(v & 0xffffffffu));
}
__device__ __forceinline__ float hi32(u64t v) {
    return __uint_as_float((unsigned)(v >> 32));
}

__global__ __launch_bounds__(128) void gemm_kernel(const float* __restrict__ W1,
                                                   const float* __restrict__ b1,
                                                   const float* __restrict__ W2,
                                                   const float* __restrict__ b2) {
    __shared__ float As[2][BK][APAD];    // [k][m]
    __shared__ float B1s[2][BK][BDUP];   // [k][2n] duplicated
    __shared__ float B2s[2][BK][BDUP];

    int tid = threadIdx.x;
    int tx = tid & 15;        // n-group: 16 * 2 = 32 n
    int ty = tid >> 4;        // m-group: 8 * 8 = 64 m
    int n0 = blockIdx.x * BN;
    int m0 = blockIdx.y * BM;

    u64t acc1[4][2] = {};     // [m-pair][n]
    u64t acc2[4][2] = {};

    int ra = tid >> 3;        // rows 0..15 (+16)
    int kk = tid & 7;         // float4 index along k

    // prologue: stage 0
#pragma unroll
    for (int i = 0; i < 4; i++) {
        int r = ra + i * 16;
        float4 v = *(const float4*)&g_y[(m0 + r) * H + kk * 4];
        As[0][kk * 4 + 0][r] = v.x; As[0][kk * 4 + 1][r] = v.y;
        As[0][kk * 4 + 2][r] = v.z; As[0][kk * 4 + 3][r] = v.w;
    }
#pragma unroll
    for (int i = 0; i < 2; i++) {
        int r = ra + i * 16;
        float4 v1 = *(const float4*)&W1[(n0 + r) * H + kk * 4];
        float4 v2 = *(const float4*)&W2[(n0 + r) * H + kk * 4];
        *(float2*)&B1s[0][kk * 4 + 0][2 * r] = make_float2(v1.x, v1.x);
        *(float2*)&B1s[0][kk * 4 + 1][2 * r] = make_float2(v1.y, v1.y);
        *(float2*)&B1s[0][kk * 4 + 2][2 * r] = make_float2(v1.z, v1.z);
        *(float2*)&B1s[0][kk * 4 + 3][2 * r] = make_float2(v1.w, v1.w);
        *(float2*)&B2s[0][kk * 4 + 0][2 * r] = make_float2(v2.x, v2.x);
        *(float2*)&B2s[0][kk * 4 + 1][2 * r] = make_float2(v2.y, v2.y);
        *(float2*)&B2s[0][kk * 4 + 2][2 * r] = make_float2(v2.z, v2.z);
        *(float2*)&B2s[0][kk * 4 + 3][2 * r] = make_float2(v2.w, v2.w);
    }
    __syncthreads();

    for (int it = 0; it < NKIT; it++) {
        int cur = it & 1;
        int nxt = cur ^ 1;

        float4 pa[4], pb1[2], pb2[2];
        if (it + 1 < NKIT) {
            int k0n = (it + 1) * BK;
#pragma unroll
            for (int i = 0; i < 4; i++)
                pa[i] = *(const float4*)&g_y[(m0 + ra + i * 16) * H + k0n + kk * 4];
#pragma unroll
            for (int i = 0; i < 2; i++) {
                pb1[i] = *(const float4*)&W1[(n0 + ra + i * 16) * H + k0n + kk * 4];
                pb2[i] = *(const float4*)&W2[(n0 + ra + i * 16) * H + k0n + kk * 4];
            }
        }

#pragma unroll
        for (int k = 0; k < BK; k++) {
            ulonglong2 a01 = *(const ulonglong2*)&As[cur][k][ty * 8];      // m-pairs 0,1
            ulonglong2 a23 = *(const ulonglong2*)&As[cur][k][ty * 8 + 4];  // m-pairs 2,3
            ulonglong2 bp1 = *(const ulonglong2*)&B1s[cur][k][tx * 4];     // dup n0, n1
            ulonglong2 bp2 = *(const ulonglong2*)&B2s[cur][k][tx * 4];
            u64t am[4] = {a01.x, a01.y, a23.x, a23.y};
#pragma unroll
            for (int i = 0; i < 4; i++) {
                acc1[i][0] = ffma2(am[i], bp1.x, acc1[i][0]);
                acc1[i][1] = ffma2(am[i], bp1.y, acc1[i][1]);
                acc2[i][0] = ffma2(am[i], bp2.x, acc2[i][0]);
                acc2[i][1] = ffma2(am[i], bp2.y, acc2[i][1]);
            }
        }

        if (it + 1 < NKIT) {
#pragma unroll
            for (int i = 0; i < 4; i++) {
                int r = ra + i * 16;
                As[nxt][kk * 4 + 0][r] = pa[i].x; As[nxt][kk * 4 + 1][r] = pa[i].y;
                As[nxt][kk * 4 + 2][r] = pa[i].z; As[nxt][kk * 4 + 3][r] = pa[i].w;
            }
#pragma unroll
            for (int i = 0; i < 2; i++) {
                int r = ra + i * 16;
                *(float2*)&B1s[nxt][kk * 4 + 0][2 * r] = make_float2(pb1[i].x, pb1[i].x);
                *(float2*)&B1s[nxt][kk * 4 + 1][2 * r] = make_float2(pb1[i].y, pb1[i].y);
                *(float2*)&B1s[nxt][kk * 4 + 2][2 * r] = make_float2(pb1[i].z, pb1[i].z);
                *(float2*)&B1s[nxt][kk * 4 + 3][2 * r] = make_float2(pb1[i].w, pb1[i].w);
                *(float2*)&B2s[nxt][kk * 4 + 0][2 * r] = make_float2(pb2[i].x, pb2[i].x);
                *(float2*)&B2s[nxt][kk * 4 + 1][2 * r] = make_float2(pb2[i].y, pb2[i].y);
                *(float2*)&B2s[nxt][kk * 4 + 2][2 * r] = make_float2(pb2[i].z, pb2[i].z);
                *(float2*)&B2s[nxt][kk * 4 + 3][2 * r] = make_float2(pb2[i].w, pb2[i].w);
            }
            __syncthreads();
        }
    }

    // Epilogue: unpack m-pairs, gate, residual add.
#pragma unroll
    for (int i = 0; i < 4; i++) {
#pragma unroll
        for (int j = 0; j < 2; j++) {
            int n = n0 + tx * 2 + j;
            float bb1 = b1[n];
            float bb2 = b2[n];
            int mA = m0 + ty * 8 + i * 2;
            float g1lo = lo32(acc1[i][j]) + bb1;
            float g1hi = hi32(acc1[i][j]) + bb1;
            float g2lo = lo32(acc2[i][j]) + bb2;
            float g2hi = hi32(acc2[i][j]) + bb2;
            float siglo = 1.f / (1.f + __expf(-g2lo));
            float sighi = 1.f / (1.f + __expf(-g2hi));
            g_h[mA * H + n]       += g1lo * siglo;
            g_h[(mA + 1) * H + n] += g1hi * sighi;
        }
    }
}

// ---------------------------------------------------------------------------
// Decoder
// ---------------------------------------------------------------------------
__global__ void dec_kernel(const float* __restrict__ w,
                           const float* __restrict__ b,
                           float* __restrict__ out) {
    int warp = (blockIdx.x * blockDim.x + threadIdx.x) >> 5;
    int lane = threadIdx.x & 31;
    if (warp >= L) return;
    float a0 = 0.f, a1 = 0.f, a2 = 0.f;
#pragma unroll
    for (int j = lane; j < H; j += 32) {
        float hv = g_h[warp * H + j];
        a0 = fmaf(hv, w[j],         a0);
        a1 = fmaf(hv, w[H + j],     a1);
        a2 = fmaf(hv, w[2 * H + j], a2);
    }
#pragma unroll
    for (int off = 16; off; off >>= 1) {
        a0 += __shfl_xor_sync(0xffffffffu, a0, off);
        a1 += __shfl_xor_sync(0xffffffffu, a1, off);
        a2 += __shfl_xor_sync(0xffffffffu, a2, off);
    }
    if (lane == 0) {
        out[warp * 3 + 0] = a0 + b[0];
        out[warp * 3 + 1] = a1 + b[1];
        out[warp * 3 + 2] = a2 + b[2];
    }
}

// ---------------------------------------------------------------------------
extern "C" void kernel_launch(void* const* d_in, const int* in_sizes, int n_in,
                              void* d_out, int out_size) {
    const float* x       = (const float*)d_in[0];
    const float* enc_w   = (const float*)d_in[1];
    const float* enc_b   = (const float*)d_in[2];
    const float* dec_w   = (const float*)d_in[3];
    const float* dec_b   = (const float*)d_in[4];
    const float* norm_w  = (const float*)d_in[5];
    const float* norm_b  = (const float*)d_in[6];
    const float* lam_re  = (const float*)d_in[7];
    const float* lam_im  = (const float*)d_in[8];
    const float* b_re    = (const float*)d_in[9];
    const float* b_im    = (const float*)d_in[10];
    const float* c_re    = (const float*)d_in[11];
    const float* c_im    = (const float*)d_in[12];
    const float* dvec    = (const float*)d_in[13];
    const float* lstep   = (const float*)d_in[14];
    const float* out_w   = (const float*)d_in[15];
    const float* out_b   = (const float*)d_in[16];
    const float* out2_w  = (const float*)d_in[17];
    const float* out2_b  = (const float*)d_in[18];
    float* out = (float*)d_out;

    enc_kernel<<<L, H>>>(x, enc_w, enc_b);

    for (int l = 0; l < NL; l++) {
        ln_kernel<<<L, 256>>>(norm_w + l * H, norm_b + l * H);
        scan_fused_kernel<<<H, 512>>>(lam_re + l * H * NSTATE, lam_im + l * H * NSTATE,
                                      b_re + l * H * NSTATE,  b_im + l * H * NSTATE,
                                      c_re + l * H * NSTATE,  c_im + l * H * NSTATE,
                                      dvec + l * H, lstep + l * H);
        dim3 grid(H / BN, L / BM);
        gemm_kernel<<<grid, 128>>>(out_w + l * H * H, out_b + l * H,
                                   out2_w + l * H * H, out2_b + l * H);
    }

    dec_kernel<<<256, 256>>>(dec_w, dec_b, out);
}

// round 10
// speedup vs baseline: 1.2734x; 1.2734x over previous
#include <cuda_runtime.h>
#include <math.h>

#define L 2048
#define H 512
#define NSTATE 32
#define NL 4
#define INDIM 4
#define OUTDIM 3

#define NCHUNK 16
#define CLEN 128   // L / NCHUNK

// Scratch (allocation-free rule: device globals)
__device__ float g_h[L * H];   // residual stream
__device__ float g_u[L * H];   // layernorm output
__device__ float g_y[L * H];   // gelu(scan output)

// Precomputed tf32 hi/lo splits of the gate weights (all layers).
// NOTE: only ever referenced from DEVICE code (host can't take their address).
__device__ float g_w1hi[NL * H * H];
__device__ float g_w1lo[NL * H * H];
__device__ float g_w2hi[NL * H * H];
__device__ float g_w2lo[NL * H * H];

// ---------------------------------------------------------------------------
// tf32 helpers
// ---------------------------------------------------------------------------
__device__ __forceinline__ unsigned cvt_tf32(float x) {
    unsigned u;
    asm("cvt.rna.tf32.f32 %0, %1;" : "=r"(u) : "f"(x));
    return u;
}

__device__ __forceinline__ void mma8(float* d,
                                     unsigned a0, unsigned a1, unsigned a2, unsigned a3,
                                     unsigned b0, unsigned b1) {
    asm("mma.sync.aligned.m16n8k8.row.col.f32.tf32.tf32.f32 "
        "{%0,%1,%2,%3},{%4,%5,%6,%7},{%8,%9},{%0,%1,%2,%3};"
        : "+f"(d[0]), "+f"(d[1]), "+f"(d[2]), "+f"(d[3])
        : "r"(a0), "r"(a1), "r"(a2), "r"(a3), "r"(b0), "r"(b1));
}

// ---------------------------------------------------------------------------
// Weight split prep: w -> (hi, lo) tf32 parts. idx over NL*H*H.
// ---------------------------------------------------------------------------
__global__ void prep_w_kernel(const float* __restrict__ w1,
                              const float* __restrict__ w2) {
    int i = blockIdx.x * blockDim.x + threadIdx.x;
    float v1 = w1[i];
    unsigned h1 = cvt_tf32(v1);
    g_w1hi[i] = __uint_as_float(h1);
    g_w1lo[i] = __uint_as_float(cvt_tf32(v1 - __uint_as_float(h1)));
    float v2 = w2[i];
    unsigned h2 = cvt_tf32(v2);
    g_w2hi[i] = __uint_as_float(h2);
    g_w2lo[i] = __uint_as_float(cvt_tf32(v2 - __uint_as_float(h2)));
}

// ---------------------------------------------------------------------------
// Encoder
// ---------------------------------------------------------------------------
__global__ void enc_kernel(const float* __restrict__ x,
                           const float* __restrict__ w,
                           const float* __restrict__ b) {
    int t = blockIdx.x;
    int j = threadIdx.x;
    float4 xr = *(const float4*)(x + t * INDIM);
    float4 wr = *(const float4*)(w + j * INDIM);
    g_h[t * H + j] = b[j] + xr.x * wr.x + xr.y * wr.y + xr.z * wr.z + xr.w * wr.w;
}

// ---------------------------------------------------------------------------
// LayerNorm over H=512 per row
// ---------------------------------------------------------------------------
__global__ void ln_kernel(const float* __restrict__ nw,
                          const float* __restrict__ nb) {
    int t = blockIdx.x;
    int tid = threadIdx.x;
    float v0 = g_h[t * H + tid];
    float v1 = g_h[t * H + tid + 256];
    float s = v0 + v1;
    float sq = v0 * v0 + v1 * v1;
#pragma unroll
    for (int off = 16; off; off >>= 1) {
        s  += __shfl_xor_sync(0xffffffffu, s, off);
        sq += __shfl_xor_sync(0xffffffffu, sq, off);
    }
    __shared__ float ss[8], ssq[8];
    int w = tid >> 5;
    if ((tid & 31) == 0) { ss[w] = s; ssq[w] = sq; }
    __syncthreads();
    __shared__ float m_sh, r_sh;
    if (tid == 0) {
        float S = 0.f, Q = 0.f;
#pragma unroll
        for (int i = 0; i < 8; i++) { S += ss[i]; Q += ssq[i]; }
        float m = S * (1.0f / H);
        float var = Q * (1.0f / H) - m * m;
        m_sh = m;
        r_sh = rsqrtf(var + 1e-5f);
    }
    __syncthreads();
    float m = m_sh, r = r_sh;
    g_u[t * H + tid]       = (v0 - m) * r * nw[tid]       + nb[tid];
    g_u[t * H + tid + 256] = (v1 - m) * r * nw[tid + 256] + nb[tid + 256];
}

// ---------------------------------------------------------------------------
// Discretization coefficients per (channel, lane=state)
// ---------------------------------------------------------------------------
struct SSMCoef { float are, aim, bbr, bbi, cre, cim, dv; };

__device__ __forceinline__ SSMCoef load_coef(
    const float* lre_, const float* lim_, const float* bre_, const float* bim_,
    const float* cre_, const float* cim_, const float* dvec, const float* lstep_,
    int ch, int lane)
{
    int idx = ch * NSTATE + lane;
    float lre = lre_[idx], lim = lim_[idx];
    float step = __expf(lstep_[ch]);
    float s2 = 0.5f * step;
    float dr = 1.f - s2 * lre, di = -s2 * lim;
    float inv = 1.f / (dr * dr + di * di);
    float blr = dr * inv, bli = -di * inv;
    float nr = 1.f + s2 * lre, ni = s2 * lim;
    SSMCoef c;
    c.are = blr * nr - bli * ni;
    c.aim = blr * ni + bli * nr;
    float br = bre_[idx], bi = bim_[idx];
    c.bbr = step * (blr * br - bli * bi);
    c.bbi = step * (blr * bi + bli * br);
    c.cre = cre_[idx];
    c.cim = cim_[idx];
    c.dv = dvec[ch];
    return c;
}

__device__ __forceinline__ float gelu_tanh(float yv) {
    float z = 0.7978845608028654f * fmaf(0.044715f * yv, yv * yv, yv);
    z = fminf(fmaxf(z, -15.f), 15.f);
    float e = __expf(2.f * z);
    float th = (e - 1.f) / (e + 1.f);
    return 0.5f * yv * (1.f + th);
}

// Merge-reduce helpers
__device__ __forceinline__ float merge2(float a, float b, int off, int lane) {
    float t = (lane & off) ? a : b;
    t = __shfl_xor_sync(0xffffffffu, t, off);
    return ((lane & off) ? b : a) + t;
}

__device__ __forceinline__ float reduce8(const float* acc, int lane) {
    float m01 = merge2(acc[0], acc[1], 16, lane);
    float m23 = merge2(acc[2], acc[3], 16, lane);
    float m45 = merge2(acc[4], acc[5], 16, lane);
    float m67 = merge2(acc[6], acc[7], 16, lane);
    float n0  = merge2(m01, m23, 8, lane);
    float n1  = merge2(m45, m67, 8, lane);
    float p   = merge2(n0, n1, 4, lane);
    p += __shfl_xor_sync(0xffffffffu, p, 2);
    p += __shfl_xor_sync(0xffffffffu, p, 1);
    return p;
}

// ---------------------------------------------------------------------------
// Fused scan: one block per channel (512 threads = 16 warps, warp = chunk).
// ---------------------------------------------------------------------------
__global__ __launch_bounds__(512) void scan_fused_kernel(
        const float* __restrict__ lre_, const float* __restrict__ lim_,
        const float* __restrict__ bre_, const float* __restrict__ bim_,
        const float* __restrict__ cre_, const float* __restrict__ cim_,
        const float* __restrict__ dvec, const float* __restrict__ lstep_) {
    __shared__ float2 st[NCHUNK][NSTATE];

    int ch = blockIdx.x;
    int wid = threadIdx.x >> 5;      // chunk
    int lane = threadIdx.x & 31;     // state

    SSMCoef cf = load_coef(lre_, lim_, bre_, bim_, cre_, cim_, dvec, lstep_, ch, lane);
    int myk = ((lane >> 4) & 1) | (((lane >> 3) & 1) << 1) | (((lane >> 2) & 1) << 2);

    int tbase = wid * CLEN;
    const float* up = g_u + ch;
    float* yp = g_y + ch;

    float yreg[16];
    float sre = 0.f, sim = 0.f;

    // ---- Phase A: local scan ----
#pragma unroll
    for (int b = 0; b < 16; b++) {
        int t0 = tbase + b * 8;
        float acc[8], uk[8];
#pragma unroll
        for (int k = 0; k < 8; k++) {
            float u = __ldg(up + (t0 + k) * H);
            float t1 = fmaf(cf.bbr, u, fmaf(-cf.aim, sim, cf.are * sre));
            float t2 = fmaf(cf.bbi, u, fmaf(cf.aim, sre, cf.are * sim));
            sre = t1; sim = t2;
            acc[k] = fmaf(-cf.cim, sim, cf.cre * sre);
            uk[k] = u;
        }
        float red = reduce8(acc, lane);
        float s01 = (lane & 16) ? uk[1] : uk[0];
        float s23 = (lane & 16) ? uk[3] : uk[2];
        float s45 = (lane & 16) ? uk[5] : uk[4];
        float s67 = (lane & 16) ? uk[7] : uk[6];
        float t0s = (lane & 8) ? s23 : s01;
        float t1s = (lane & 8) ? s67 : s45;
        float usel = (lane & 4) ? t1s : t0s;
        yreg[b] = fmaf(cf.dv, usel, 2.f * red);
    }
    st[wid][lane] = make_float2(sre, sim);
    __syncthreads();

    // ---- Phase B: sequential chunk combine (warp 0) ----
    if (wid == 0) {
        float pr = cf.are, pi = cf.aim;
#pragma unroll
        for (int i = 0; i < 7; i++) {   // A^128
            float nr = pr * pr - pi * pi;
            float ni = 2.f * pr * pi;
            pr = nr; pi = ni;
        }
        float cr = 0.f, ci = 0.f;
#pragma unroll
        for (int c = 0; c < NCHUNK; c++) {
            float2 f = st[c][lane];
            st[c][lane] = make_float2(cr, ci);
            float nr = fmaf(pr, cr, fmaf(-pi, ci, f.x));
            float ni = fmaf(pr, ci, fmaf(pi, cr, f.y));
            cr = nr; ci = ni;
        }
    }
    __syncthreads();

    // ---- Phase C: correction + gelu + store ----
    float2 si = st[wid][lane];
    float er = cf.cre * si.x - cf.cim * si.y;
    float ei = cf.cre * si.y + cf.cim * si.x;
    float wr = 1.f, wi = 0.f;

#pragma unroll
    for (int b = 0; b < 16; b++) {
        float acc[8];
#pragma unroll
        for (int k = 0; k < 8; k++) {
            float nr = cf.are * wr - cf.aim * wi;
            float ni = cf.are * wi + cf.aim * wr;
            wr = nr; wi = ni;
            acc[k] = er * wr - ei * wi;
        }
        float corr = reduce8(acc, lane);
        float yv = yreg[b] + 2.f * corr;
        if ((lane & 3) == 0)
            yp[(tbase + b * 8 + myk) * H] = gelu_tanh(yv);
    }
}

// ---------------------------------------------------------------------------
// Dual GEMM via tf32 mma.sync (3xTF32 precision). BM=64, BN=32, BK=16.
// 128 threads = 4 warps in 2x2 (warp tile 32m x 16n). 512 blocks.
// Weight hi/lo splits resolved from device globals via layer index (the
// round-9 bug was passing __device__ symbol addresses from host code).
// ---------------------------------------------------------------------------
#define BM 64
#define BN 32
#define BK 16
#define ASTR 20          // row stride (floats): bank = 4g+t, conflict-free
#define NKIT (H / BK)

__global__ __launch_bounds__(128) void gemm_kernel(int layer,
                                                   const float* __restrict__ b1,
                                                   const float* __restrict__ b2) {
    const float* __restrict__ W1hi = g_w1hi + layer * H * H;
    const float* __restrict__ W1lo = g_w1lo + layer * H * H;
    const float* __restrict__ W2hi = g_w2hi + layer * H * H;
    const float* __restrict__ W2lo = g_w2lo + layer * H * H;

    __shared__ float As[2][BM][ASTR];
    __shared__ float B1h[2][BN][ASTR];
    __shared__ float B1l[2][BN][ASTR];
    __shared__ float B2h[2][BN][ASTR];
    __shared__ float B2l[2][BN][ASTR];

    int tid = threadIdx.x;
    int wrp = tid >> 5;
    int lane = tid & 31;
    int g = lane >> 2;       // group id (0..7)
    int t = lane & 3;        // thread in group
    int wm = wrp >> 1;       // 0..1 -> m offset 32*wm
    int wn = wrp & 1;        // 0..1 -> n offset 16*wn
    int n0 = blockIdx.x * BN;
    int m0 = blockIdx.y * BM;

    float d1[2][2][4] = {};  // [mt][nt][frag]
    float d2[2][2][4] = {};

    int raA = tid >> 2;      // 0..31 (+32)
    int kqA = tid & 3;
    int raB = tid >> 2;
    int kqB = tid & 3;

    // prologue: stage 0
    {
#pragma unroll
        for (int i = 0; i < 2; i++) {
            int r = raA + i * 32;
            float4 v = *(const float4*)&g_y[(m0 + r) * H + kqA * 4];
            *(float4*)&As[0][r][kqA * 4] = v;
        }
        float4 vb;
        vb = *(const float4*)&W1hi[(n0 + raB) * H + kqB * 4];
        *(float4*)&B1h[0][raB][kqB * 4] = vb;
        vb = *(const float4*)&W1lo[(n0 + raB) * H + kqB * 4];
        *(float4*)&B1l[0][raB][kqB * 4] = vb;
        vb = *(const float4*)&W2hi[(n0 + raB) * H + kqB * 4];
        *(float4*)&B2h[0][raB][kqB * 4] = vb;
        vb = *(const float4*)&W2lo[(n0 + raB) * H + kqB * 4];
        *(float4*)&B2l[0][raB][kqB * 4] = vb;
    }
    __syncthreads();

    for (int it = 0; it < NKIT; it++) {
        int cur = it & 1;
        int nxt = cur ^ 1;

        float4 pa[2], pb1h, pb1l, pb2h, pb2l;
        if (it + 1 < NKIT) {
            int k0n = (it + 1) * BK;
#pragma unroll
            for (int i = 0; i < 2; i++)
                pa[i] = *(const float4*)&g_y[(m0 + raA + i * 32) * H + k0n + kqA * 4];
            pb1h = *(const float4*)&W1hi[(n0 + raB) * H + k0n + kqB * 4];
            pb1l = *(const float4*)&W1lo[(n0 + raB) * H + k0n + kqB * 4];
            pb2h = *(const float4*)&W2hi[(n0 + raB) * H + k0n + kqB * 4];
            pb2l = *(const float4*)&W2lo[(n0 + raB) * H + k0n + kqB * 4];
        }

#pragma unroll
        for (int kt = 0; kt < 2; kt++) {
            int k8 = kt * 8;
            unsigned ahi[2][4], alo[2][4];
#pragma unroll
            for (int mt = 0; mt < 2; mt++) {
                int rm = wm * 32 + mt * 16;
                float af0 = As[cur][rm + g][k8 + t];
                float af1 = As[cur][rm + g + 8][k8 + t];
                float af2 = As[cur][rm + g][k8 + t + 4];
                float af3 = As[cur][rm + g + 8][k8 + t + 4];
                ahi[mt][0] = cvt_tf32(af0);
                ahi[mt][1] = cvt_tf32(af1);
                ahi[mt][2] = cvt_tf32(af2);
                ahi[mt][3] = cvt_tf32(af3);
                alo[mt][0] = cvt_tf32(af0 - __uint_as_float(ahi[mt][0]));
                alo[mt][1] = cvt_tf32(af1 - __uint_as_float(ahi[mt][1]));
                alo[mt][2] = cvt_tf32(af2 - __uint_as_float(ahi[mt][2]));
                alo[mt][3] = cvt_tf32(af3 - __uint_as_float(ahi[mt][3]));
            }
#pragma unroll
            for (int nt = 0; nt < 2; nt++) {
                int nb = wn * 16 + nt * 8;
                unsigned b1h0 = __float_as_uint(B1h[cur][nb + g][k8 + t]);
                unsigned b1h1 = __float_as_uint(B1h[cur][nb + g][k8 + t + 4]);
                unsigned b1l0 = __float_as_uint(B1l[cur][nb + g][k8 + t]);
                unsigned b1l1 = __float_as_uint(B1l[cur][nb + g][k8 + t + 4]);
                unsigned b2h0 = __float_as_uint(B2h[cur][nb + g][k8 + t]);
                unsigned b2h1 = __float_as_uint(B2h[cur][nb + g][k8 + t + 4]);
                unsigned b2l0 = __float_as_uint(B2l[cur][nb + g][k8 + t]);
                unsigned b2l1 = __float_as_uint(B2l[cur][nb + g][k8 + t + 4]);
#pragma unroll
                for (int mt = 0; mt < 2; mt++) {
                    mma8(d1[mt][nt], ahi[mt][0], ahi[mt][1], ahi[mt][2], ahi[mt][3], b1h0, b1h1);
                    mma8(d1[mt][nt], ahi[mt][0], ahi[mt][1], ahi[mt][2], ahi[mt][3], b1l0, b1l1);
                    mma8(d1[mt][nt], alo[mt][0], alo[mt][1], alo[mt][2], alo[mt][3], b1h0, b1h1);
                    mma8(d2[mt][nt], ahi[mt][0], ahi[mt][1], ahi[mt][2], ahi[mt][3], b2h0, b2h1);
                    mma8(d2[mt][nt], ahi[mt][0], ahi[mt][1], ahi[mt][2], ahi[mt][3], b2l0, b2l1);
                    mma8(d2[mt][nt], alo[mt][0], alo[mt][1], alo[mt][2], alo[mt][3], b2h0, b2h1);
                }
            }
        }

        if (it + 1 < NKIT) {
#pragma unroll
            for (int i = 0; i < 2; i++)
                *(float4*)&As[nxt][raA + i * 32][kqA * 4] = pa[i];
            *(float4*)&B1h[nxt][raB][kqB * 4] = pb1h;
            *(float4*)&B1l[nxt][raB][kqB * 4] = pb1l;
            *(float4*)&B2h[nxt][raB][kqB * 4] = pb2h;
            *(float4*)&B2l[nxt][raB][kqB * 4] = pb2l;
            __syncthreads();
        }
    }

    // Epilogue: gate + residual.
#pragma unroll
    for (int mt = 0; mt < 2; mt++) {
#pragma unroll
        for (int nt = 0; nt < 2; nt++) {
            int row0 = m0 + wm * 32 + mt * 16 + g;
            int col0 = n0 + wn * 16 + nt * 8 + 2 * t;
            float bb1a = b1[col0], bb1b = b1[col0 + 1];
            float bb2a = b2[col0], bb2b = b2[col0 + 1];
            {
                float g1 = d1[mt][nt][0] + bb1a;
                float g2 = d2[mt][nt][0] + bb2a;
                g_h[row0 * H + col0] += g1 * (1.f / (1.f + __expf(-g2)));
                g1 = d1[mt][nt][1] + bb1b;
                g2 = d2[mt][nt][1] + bb2b;
                g_h[row0 * H + col0 + 1] += g1 * (1.f / (1.f + __expf(-g2)));
            }
            {
                int r8 = row0 + 8;
                float g1 = d1[mt][nt][2] + bb1a;
                float g2 = d2[mt][nt][2] + bb2a;
                g_h[r8 * H + col0] += g1 * (1.f / (1.f + __expf(-g2)));
                g1 = d1[mt][nt][3] + bb1b;
                g2 = d2[mt][nt][3] + bb2b;
                g_h[r8 * H + col0 + 1] += g1 * (1.f / (1.f + __expf(-g2)));
            }
        }
    }
}

// ---------------------------------------------------------------------------
// Decoder
// ---------------------------------------------------------------------------
__global__ void dec_kernel(const float* __restrict__ w,
                           const float* __restrict__ b,
                           float* __restrict__ out) {
    int warp = (blockIdx.x * blockDim.x + threadIdx.x) >> 5;
    int lane = threadIdx.x & 31;
    if (warp >= L) return;
    float a0 = 0.f, a1 = 0.f, a2 = 0.f;
#pragma unroll
    for (int j = lane; j < H; j += 32) {
        float hv = g_h[warp * H + j];
        a0 = fmaf(hv, w[j],         a0);
        a1 = fmaf(hv, w[H + j],     a1);
        a2 = fmaf(hv, w[2 * H + j], a2);
    }
#pragma unroll
    for (int off = 16; off; off >>= 1) {
        a0 += __shfl_xor_sync(0xffffffffu, a0, off);
        a1 += __shfl_xor_sync(0xffffffffu, a1, off);
        a2 += __shfl_xor_sync(0xffffffffu, a2, off);
    }
    if (lane == 0) {
        out[warp * 3 + 0] = a0 + b[0];
        out[warp * 3 + 1] = a1 + b[1];
        out[warp * 3 + 2] = a2 + b[2];
    }
}

// ---------------------------------------------------------------------------
extern "C" void kernel_launch(void* const* d_in, const int* in_sizes, int n_in,
                              void* d_out, int out_size) {
    const float* x       = (const float*)d_in[0];
    const float* enc_w   = (const float*)d_in[1];
    const float* enc_b   = (const float*)d_in[2];
    const float* dec_w   = (const float*)d_in[3];
    const float* dec_b   = (const float*)d_in[4];
    const float* norm_w  = (const float*)d_in[5];
    const float* norm_b  = (const float*)d_in[6];
    const float* lam_re  = (const float*)d_in[7];
    const float* lam_im  = (const float*)d_in[8];
    const float* b_re    = (const float*)d_in[9];
    const float* b_im    = (const float*)d_in[10];
    const float* c_re    = (const float*)d_in[11];
    const float* c_im    = (const float*)d_in[12];
    const float* dvec    = (const float*)d_in[13];
    const float* lstep   = (const float*)d_in[14];
    const float* out_w   = (const float*)d_in[15];
    const float* out_b   = (const float*)d_in[16];
    const float* out2_w  = (const float*)d_in[17];
    const float* out2_b  = (const float*)d_in[18];
    float* out = (float*)d_out;

    prep_w_kernel<<<(NL * H * H) / 256, 256>>>(out_w, out2_w);
    enc_kernel<<<L, H>>>(x, enc_w, enc_b);

    for (int l = 0; l < NL; l++) {
        ln_kernel<<<L, 256>>>(norm_w + l * H, norm_b + l * H);
        scan_fused_kernel<<<H, 512>>>(lam_re + l * H * NSTATE, lam_im + l * H * NSTATE,
                                      b_re + l * H * NSTATE,  b_im + l * H * NSTATE,
                                      c_re + l * H * NSTATE,  c_im + l * H * NSTATE,
                                      dvec + l * H, lstep + l * H);
        dim3 grid(H / BN, L / BM);
        gemm_kernel<<<grid, 128>>>(l, out_b + l * H, out2_b + l * H);
    }

    dec_kernel<<<256, 256>>>(dec_w, dec_b, out);
}

// round 12
// speedup vs baseline: 1.2912x; 1.0140x over previous
#include <cuda_runtime.h>
#include <math.h>

#define L 2048
#define H 512
#define NSTATE 32
#define NL 4
#define INDIM 4
#define OUTDIM 3

#define NCHUNK 16
#define CLEN 128   // L / NCHUNK

// Scratch (allocation-free rule: device globals)
__device__ float g_h[L * H];   // residual stream
__device__ float g_u[L * H];   // layernorm output
__device__ float g_y[L * H];   // gelu(scan output)

// Precomputed tf32 hi/lo splits of the gate weights (all layers).
// NOTE: only ever referenced from DEVICE code.
__device__ float g_w1hi[NL * H * H];
__device__ float g_w1lo[NL * H * H];
__device__ float g_w2hi[NL * H * H];
__device__ float g_w2lo[NL * H * H];

// ---------------------------------------------------------------------------
// tf32 helpers
// ---------------------------------------------------------------------------
__device__ __forceinline__ unsigned cvt_tf32(float x) {
    unsigned u;
    asm("cvt.rna.tf32.f32 %0, %1;" : "=r"(u) : "f"(x));
    return u;
}

__device__ __forceinline__ void mma8(float* d,
                                     unsigned a0, unsigned a1, unsigned a2, unsigned a3,
                                     unsigned b0, unsigned b1) {
    asm("mma.sync.aligned.m16n8k8.row.col.f32.tf32.tf32.f32 "
        "{%0,%1,%2,%3},{%4,%5,%6,%7},{%8,%9},{%0,%1,%2,%3};"
        : "+f"(d[0]), "+f"(d[1]), "+f"(d[2]), "+f"(d[3])
        : "r"(a0), "r"(a1), "r"(a2), "r"(a3), "r"(b0), "r"(b1));
}

// ---------------------------------------------------------------------------
// Weight split prep: w -> (hi, lo) tf32 parts. idx over NL*H*H.
// ---------------------------------------------------------------------------
__global__ void prep_w_kernel(const float* __restrict__ w1,
                              const float* __restrict__ w2) {
    int i = blockIdx.x * blockDim.x + threadIdx.x;
    float v1 = w1[i];
    unsigned h1 = cvt_tf32(v1);
    g_w1hi[i] = __uint_as_float(h1);
    g_w1lo[i] = __uint_as_float(cvt_tf32(v1 - __uint_as_float(h1)));
    float v2 = w2[i];
    unsigned h2 = cvt_tf32(v2);
    g_w2hi[i] = __uint_as_float(h2);
    g_w2lo[i] = __uint_as_float(cvt_tf32(v2 - __uint_as_float(h2)));
}

// ---------------------------------------------------------------------------
// Encoder
// ---------------------------------------------------------------------------
__global__ void enc_kernel(const float* __restrict__ x,
                           const float* __restrict__ w,
                           const float* __restrict__ b) {
    int t = blockIdx.x;
    int j = threadIdx.x;
    float4 xr = *(const float4*)(x + t * INDIM);
    float4 wr = *(const float4*)(w + j * INDIM);
    g_h[t * H + j] = b[j] + xr.x * wr.x + xr.y * wr.y + xr.z * wr.z + xr.w * wr.w;
}

// ---------------------------------------------------------------------------
// LayerNorm over H=512 per row
// ---------------------------------------------------------------------------
__global__ void ln_kernel(const float* __restrict__ nw,
                          const float* __restrict__ nb) {
    int t = blockIdx.x;
    int tid = threadIdx.x;
    float v0 = g_h[t * H + tid];
    float v1 = g_h[t * H + tid + 256];
    float s = v0 + v1;
    float sq = v0 * v0 + v1 * v1;
#pragma unroll
    for (int off = 16; off; off >>= 1) {
        s  += __shfl_xor_sync(0xffffffffu, s, off);
        sq += __shfl_xor_sync(0xffffffffu, sq, off);
    }
    __shared__ float ss[8], ssq[8];
    int w = tid >> 5;
    if ((tid & 31) == 0) { ss[w] = s; ssq[w] = sq; }
    __syncthreads();
    __shared__ float m_sh, r_sh;
    if (tid == 0) {
        float S = 0.f, Q = 0.f;
#pragma unroll
        for (int i = 0; i < 8; i++) { S += ss[i]; Q += ssq[i]; }
        float m = S * (1.0f / H);
        float var = Q * (1.0f / H) - m * m;
        m_sh = m;
        r_sh = rsqrtf(var + 1e-5f);
    }
    __syncthreads();
    float m = m_sh, r = r_sh;
    g_u[t * H + tid]       = (v0 - m) * r * nw[tid]       + nb[tid];
    g_u[t * H + tid + 256] = (v1 - m) * r * nw[tid + 256] + nb[tid + 256];
}

// ---------------------------------------------------------------------------
// Discretization coefficients per (channel, lane=state)
// ---------------------------------------------------------------------------
struct SSMCoef { float are, aim, bbr, bbi, cre, cim, dv; };

__device__ __forceinline__ SSMCoef load_coef(
    const float* lre_, const float* lim_, const float* bre_, const float* bim_,
    const float* cre_, const float* cim_, const float* dvec, const float* lstep_,
    int ch, int lane)
{
    int idx = ch * NSTATE + lane;
    float lre = lre_[idx], lim = lim_[idx];
    float step = __expf(lstep_[ch]);
    float s2 = 0.5f * step;
    float dr = 1.f - s2 * lre, di = -s2 * lim;
    float inv = 1.f / (dr * dr + di * di);
    float blr = dr * inv, bli = -di * inv;
    float nr = 1.f + s2 * lre, ni = s2 * lim;
    SSMCoef c;
    c.are = blr * nr - bli * ni;
    c.aim = blr * ni + bli * nr;
    float br = bre_[idx], bi = bim_[idx];
    c.bbr = step * (blr * br - bli * bi);
    c.bbi = step * (blr * bi + bli * br);
    c.cre = cre_[idx];
    c.cim = cim_[idx];
    c.dv = dvec[ch];
    return c;
}

__device__ __forceinline__ float gelu_tanh(float yv) {
    float z = 0.7978845608028654f * fmaf(0.044715f * yv, yv * yv, yv);
    z = fminf(fmaxf(z, -15.f), 15.f);
    float e = __expf(2.f * z);
    float th = (e - 1.f) / (e + 1.f);
    return 0.5f * yv * (1.f + th);
}

// Merge-reduce helpers
__device__ __forceinline__ float merge2(float a, float b, int off, int lane) {
    float t = (lane & off) ? a : b;
    t = __shfl_xor_sync(0xffffffffu, t, off);
    return ((lane & off) ? b : a) + t;
}

// Reduce 8 accumulators across the warp with 9 shuffles. Result: each lane
// holds the full 32-lane sum of acc[myk], myk = bit16 + 2*bit8 + 4*bit4.
__device__ __forceinline__ float reduce8(const float* acc, int lane) {
    float m01 = merge2(acc[0], acc[1], 16, lane);
    float m23 = merge2(acc[2], acc[3], 16, lane);
    float m45 = merge2(acc[4], acc[5], 16, lane);
    float m67 = merge2(acc[6], acc[7], 16, lane);
    float n0  = merge2(m01, m23, 8, lane);
    float n1  = merge2(m45, m67, 8, lane);
    float p   = merge2(n0, n1, 4, lane);
    p += __shfl_xor_sync(0xffffffffu, p, 2);
    p += __shfl_xor_sync(0xffffffffu, p, 1);
    return p;
}

// ---------------------------------------------------------------------------
// Fused scan: one block per channel (512 threads = 16 warps, warp = chunk).
// Phase A folds the d*u term into the reduction (lane k adds 0.5*dv*u_k).
// Phase C tracks p = C*s_init*A^(k+1) so the correction is Re(p) for free.
// ---------------------------------------------------------------------------
__global__ __launch_bounds__(512) void scan_fused_kernel(
        const float* __restrict__ lre_, const float* __restrict__ lim_,
        const float* __restrict__ bre_, const float* __restrict__ bim_,
        const float* __restrict__ cre_, const float* __restrict__ cim_,
        const float* __restrict__ dvec, const float* __restrict__ lstep_) {
    __shared__ float2 st[NCHUNK][NSTATE];

    int ch = blockIdx.x;
    int wid = threadIdx.x >> 5;      // chunk
    int lane = threadIdx.x & 31;     // state

    SSMCoef cf = load_coef(lre_, lim_, bre_, bim_, cre_, cim_, dvec, lstep_, ch, lane);
    int myk = ((lane >> 4) & 1) | (((lane >> 3) & 1) << 1) | (((lane >> 2) & 1) << 2);
    float hdv = 0.5f * cf.dv;

    int tbase = wid * CLEN;
    const float* up = g_u + ch;
    float* yp = g_y + ch;

    float yreg[16];
    float sre = 0.f, sim = 0.f;

    // ---- Phase A: local scan ----
#pragma unroll
    for (int b = 0; b < 16; b++) {
        int t0 = tbase + b * 8;
        float acc[8];
#pragma unroll
        for (int k = 0; k < 8; k++) {
            float u = __ldg(up + (t0 + k) * H);
            float t1 = fmaf(cf.bbr, u, fmaf(-cf.aim, sim, cf.are * sre));
            float t2 = fmaf(cf.bbi, u, fmaf(cf.aim, sre, cf.are * sim));
            sre = t1; sim = t2;
            acc[k] = fmaf(-cf.cim, sim, cf.cre * sre);
            if (lane == k) acc[k] = fmaf(hdv, u, acc[k]);   // fold d*u (div by 2 since y=2*red)
        }
        yreg[b] = 2.f * reduce8(acc, lane);   // meaningful on lane's myk slot
    }
    st[wid][lane] = make_float2(sre, sim);
    __syncthreads();

    // ---- Phase B: sequential chunk combine (warp 0) ----
    if (wid == 0) {
        float pr = cf.are, pi = cf.aim;
#pragma unroll
        for (int i = 0; i < 7; i++) {   // A^128
            float nr = pr * pr - pi * pi;
            float ni = 2.f * pr * pi;
            pr = nr; pi = ni;
        }
        float cr = 0.f, ci = 0.f;
#pragma unroll
        for (int c = 0; c < NCHUNK; c++) {
            float2 f = st[c][lane];
            st[c][lane] = make_float2(cr, ci);
            float nr = fmaf(pr, cr, fmaf(-pi, ci, f.x));
            float ni = fmaf(pr, ci, fmaf(pi, cr, f.y));
            cr = nr; ci = ni;
        }
    }
    __syncthreads();

    // ---- Phase C: correction + gelu + store ----
    float2 si = st[wid][lane];
    float pr = cf.cre * si.x - cf.cim * si.y;   // p = C*s_init (will become C*s_init*A^(t+1))
    float pi = cf.cre * si.y + cf.cim * si.x;

#pragma unroll
    for (int b = 0; b < 16; b++) {
        float acc[8];
#pragma unroll
        for (int k = 0; k < 8; k++) {
            float nr = pr * cf.are - pi * cf.aim;
            float ni = pr * cf.aim + pi * cf.are;
            pr = nr; pi = ni;
            acc[k] = nr;                         // Re(p) — free
        }
        float corr = reduce8(acc, lane);
        if ((lane & 3) == 0) {
            float yv = yreg[b] + 2.f * corr;
            yp[(tbase + b * 8 + myk) * H] = gelu_tanh(yv);
        }
    }
}

// ---------------------------------------------------------------------------
// Dual GEMM via tf32 mma.sync (3xTF32 precision). BM=64, BN=32, BK=16.
// 128 threads = 4 warps in 2x2 (warp tile 32m x 16n). 512 blocks.
// ---------------------------------------------------------------------------
#define BM 64
#define BN 32
#define BK 16
#define ASTR 20          // row stride (floats): conflict-free
#define NKIT (H / BK)

__global__ __launch_bounds__(128) void gemm_kernel(int layer,
                                                   const float* __restrict__ b1,
                                                   const float* __restrict__ b2) {
    const float* __restrict__ W1hi = g_w1hi + layer * H * H;
    const float* __restrict__ W1lo = g_w1lo + layer * H * H;
    const float* __restrict__ W2hi = g_w2hi + layer * H * H;
    const float* __restrict__ W2lo = g_w2lo + layer * H * H;

    __shared__ float As[2][BM][ASTR];
    __shared__ float B1h[2][BN][ASTR];
    __shared__ float B1l[2][BN][ASTR];
    __shared__ float B2h[2][BN][ASTR];
    __shared__ float B2l[2][BN][ASTR];

    int tid = threadIdx.x;
    int wrp = tid >> 5;
    int lane = tid & 31;
    int g = lane >> 2;       // group id (0..7)
    int t = lane & 3;        // thread in group
    int wm = wrp >> 1;
    int wn = wrp & 1;
    int n0 = blockIdx.x * BN;
    int m0 = blockIdx.y * BM;

    float d1[2][2][4] = {};
    float d2[2][2][4] = {};

    int raA = tid >> 2;      // 0..31 (+32)
    int kqA = tid & 3;
    int raB = tid >> 2;
    int kqB = tid & 3;

    // prologue: stage 0
    {
#pragma unroll
        for (int i = 0; i < 2; i++) {
            int r = raA + i * 32;
            float4 v = *(const float4*)&g_y[(m0 + r) * H + kqA * 4];
            *(float4*)&As[0][r][kqA * 4] = v;
        }
        float4 vb;
        vb = *(const float4*)&W1hi[(n0 + raB) * H + kqB * 4];
        *(float4*)&B1h[0][raB][kqB * 4] = vb;
        vb = *(const float4*)&W1lo[(n0 + raB) * H + kqB * 4];
        *(float4*)&B1l[0][raB][kqB * 4] = vb;
        vb = *(const float4*)&W2hi[(n0 + raB) * H + kqB * 4];
        *(float4*)&B2h[0][raB][kqB * 4] = vb;
        vb = *(const float4*)&W2lo[(n0 + raB) * H + kqB * 4];
        *(float4*)&B2l[0][raB][kqB * 4] = vb;
    }
    __syncthreads();

    for (int it = 0; it < NKIT; it++) {
        int cur = it & 1;
        int nxt = cur ^ 1;

        float4 pa[2], pb1h, pb1l, pb2h, pb2l;
        if (it + 1 < NKIT) {
            int k0n = (it + 1) * BK;
#pragma unroll
            for (int i = 0; i < 2; i++)
                pa[i] = *(const float4*)&g_y[(m0 + raA + i * 32) * H + k0n + kqA * 4];
            pb1h = *(const float4*)&W1hi[(n0 + raB) * H + k0n + kqB * 4];
            pb1l = *(const float4*)&W1lo[(n0 + raB) * H + k0n + kqB * 4];
            pb2h = *(const float4*)&W2hi[(n0 + raB) * H + k0n + kqB * 4];
            pb2l = *(const float4*)&W2lo[(n0 + raB) * H + k0n + kqB * 4];
        }

#pragma unroll
        for (int kt = 0; kt < 2; kt++) {
            int k8 = kt * 8;
            unsigned ahi[2][4], alo[2][4];
#pragma unroll
            for (int mt = 0; mt < 2; mt++) {
                int rm = wm * 32 + mt * 16;
                float af0 = As[cur][rm + g][k8 + t];
                float af1 = As[cur][rm + g + 8][k8 + t];
                float af2 = As[cur][rm + g][k8 + t + 4];
                float af3 = As[cur][rm + g + 8][k8 + t + 4];
                ahi[mt][0] = cvt_tf32(af0);
                ahi[mt][1] = cvt_tf32(af1);
                ahi[mt][2] = cvt_tf32(af2);
                ahi[mt][3] = cvt_tf32(af3);
                alo[mt][0] = cvt_tf32(af0 - __uint_as_float(ahi[mt][0]));
                alo[mt][1] = cvt_tf32(af1 - __uint_as_float(ahi[mt][1]));
                alo[mt][2] = cvt_tf32(af2 - __uint_as_float(ahi[mt][2]));
                alo[mt][3] = cvt_tf32(af3 - __uint_as_float(ahi[mt][3]));
            }
#pragma unroll
            for (int nt = 0; nt < 2; nt++) {
                int nb = wn * 16 + nt * 8;
                unsigned b1h0 = __float_as_uint(B1h[cur][nb + g][k8 + t]);
                unsigned b1h1 = __float_as_uint(B1h[cur][nb + g][k8 + t + 4]);
                unsigned b1l0 = __float_as_uint(B1l[cur][nb + g][k8 + t]);
                unsigned b1l1 = __float_as_uint(B1l[cur][nb + g][k8 + t + 4]);
                unsigned b2h0 = __float_as_uint(B2h[cur][nb + g][k8 + t]);
                unsigned b2h1 = __float_as_uint(B2h[cur][nb + g][k8 + t + 4]);
                unsigned b2l0 = __float_as_uint(B2l[cur][nb + g][k8 + t]);
                unsigned b2l1 = __float_as_uint(B2l[cur][nb + g][k8 + t + 4]);
#pragma unroll
                for (int mt = 0; mt < 2; mt++) {
                    mma8(d1[mt][nt], ahi[mt][0], ahi[mt][1], ahi[mt][2], ahi[mt][3], b1h0, b1h1);
                    mma8(d1[mt][nt], ahi[mt][0], ahi[mt][1], ahi[mt][2], ahi[mt][3], b1l0, b1l1);
                    mma8(d1[mt][nt], alo[mt][0], alo[mt][1], alo[mt][2], alo[mt][3], b1h0, b1h1);
                    mma8(d2[mt][nt], ahi[mt][0], ahi[mt][1], ahi[mt][2], ahi[mt][3], b2h0, b2h1);
                    mma8(d2[mt][nt], ahi[mt][0], ahi[mt][1], ahi[mt][2], ahi[mt][3], b2l0, b2l1);
                    mma8(d2[mt][nt], alo[mt][0], alo[mt][1], alo[mt][2], alo[mt][3], b2h0, b2h1);
                }
            }
        }

        if (it + 1 < NKIT) {
#pragma unroll
            for (int i = 0; i < 2; i++)
                *(float4*)&As[nxt][raA + i * 32][kqA * 4] = pa[i];
            *(float4*)&B1h[nxt][raB][kqB * 4] = pb1h;
            *(float4*)&B1l[nxt][raB][kqB * 4] = pb1l;
            *(float4*)&B2h[nxt][raB][kqB * 4] = pb2h;
            *(float4*)&B2l[nxt][raB][kqB * 4] = pb2l;
            __syncthreads();
        }
    }

    // Epilogue: gate + residual.
#pragma unroll
    for (int mt = 0; mt < 2; mt++) {
#pragma unroll
        for (int nt = 0; nt < 2; nt++) {
            int row0 = m0 + wm * 32 + mt * 16 + g;
            int col0 = n0 + wn * 16 + nt * 8 + 2 * t;
            float bb1a = b1[col0], bb1b = b1[col0 + 1];
            float bb2a = b2[col0], bb2b = b2[col0 + 1];
            {
                float g1 = d1[mt][nt][0] + bb1a;
                float g2 = d2[mt][nt][0] + bb2a;
                g_h[row0 * H + col0] += g1 * (1.f / (1.f + __expf(-g2)));
                g1 = d1[mt][nt][1] + bb1b;
                g2 = d2[mt][nt][1] + bb2b;
                g_h[row0 * H + col0 + 1] += g1 * (1.f / (1.f + __expf(-g2)));
            }
            {
                int r8 = row0 + 8;
                float g1 = d1[mt][nt][2] + bb1a;
                float g2 = d2[mt][nt][2] + bb2a;
                g_h[r8 * H + col0] += g1 * (1.f / (1.f + __expf(-g2)));
                g1 = d1[mt][nt][3] + bb1b;
                g2 = d2[mt][nt][3] + bb2b;
                g_h[r8 * H + col0 + 1] += g1 * (1.f / (1.f + __expf(-g2)));
            }
        }
    }
}

// ---------------------------------------------------------------------------
// Decoder
// ---------------------------------------------------------------------------
__global__ void dec_kernel(const float* __restrict__ w,
                           const float* __restrict__ b,
                           float* __restrict__ out) {
    int warp = (blockIdx.x * blockDim.x + threadIdx.x) >> 5;
    int lane = threadIdx.x & 31;
    if (warp >= L) return;
    float a0 = 0.f, a1 = 0.f, a2 = 0.f;
#pragma unroll
    for (int j = lane; j < H; j += 32) {
        float hv = g_h[warp * H + j];
        a0 = fmaf(hv, w[j],         a0);
        a1 = fmaf(hv, w[H + j],     a1);
        a2 = fmaf(hv, w[2 * H + j], a2);
    }
#pragma unroll
    for (int off = 16; off; off >>= 1) {
        a0 += __shfl_xor_sync(0xffffffffu, a0, off);
        a1 += __shfl_xor_sync(0xffffffffu, a1, off);
        a2 += __shfl_xor_sync(0xffffffffu, a2, off);
    }
    if (lane == 0) {
        out[warp * 3 + 0] = a0 + b[0];
        out[warp * 3 + 1] = a1 + b[1];
        out[warp * 3 + 2] = a2 + b[2];
    }
}

// ---------------------------------------------------------------------------
extern "C" void kernel_launch(void* const* d_in, const int* in_sizes, int n_in,
                              void* d_out, int out_size) {
    const float* x       = (const float*)d_in[0];
    const float* enc_w   = (const float*)d_in[1];
    const float* enc_b   = (const float*)d_in[2];
    const float* dec_w   = (const float*)d_in[3];
    const float* dec_b   = (const float*)d_in[4];
    const float* norm_w  = (const float*)d_in[5];
    const float* norm_b  = (const float*)d_in[6];
    const float* lam_re  = (const float*)d_in[7];
    const float* lam_im  = (const float*)d_in[8];
    const float* b_re    = (const float*)d_in[9];
    const float* b_im    = (const float*)d_in[10];
    const float* c_re    = (const float*)d_in[11];
    const float* c_im    = (const float*)d_in[12];
    const float* dvec    = (const float*)d_in[13];
    const float* lstep   = (const float*)d_in[14];
    const float* out_w   = (const float*)d_in[15];
    const float* out_b   = (const float*)d_in[16];
    const float* out2_w  = (const float*)d_in[17];
    const float* out2_b  = (const float*)d_in[18];
    float* out = (float*)d_out;

    prep_w_kernel<<<(NL * H * H) / 256, 256>>>(out_w, out2_w);
    enc_kernel<<<L, H>>>(x, enc_w, enc_b);

    for (int l = 0; l < NL; l++) {
        ln_kernel<<<L, 256>>>(norm_w + l * H, norm_b + l * H);
        scan_fused_kernel<<<H, 512>>>(lam_re + l * H * NSTATE, lam_im + l * H * NSTATE,
                                      b_re + l * H * NSTATE,  b_im + l * H * NSTATE,
                                      c_re + l * H * NSTATE,  c_im + l * H * NSTATE,
                                      dvec + l * H, lstep + l * H);
        dim3 grid(H / BN, L / BM);
        gemm_kernel<<<grid, 128>>>(l, out_b + l * H, out2_b + l * H);
    }

    dec_kernel<<<256, 256>>>(dec_w, dec_b, out);
}